// round 14
// baseline (speedup 1.0000x reference)
#include <cuda_runtime.h>
#include <cuda_fp16.h>
#include <cstdint>

#define CIN   32
#define COUT  32
#define HDIM  64
#define WDIM  64
#define TM    8       // tile rows (y)
#define TN    16      // tile cols (x)
#define NTHR  256
#define XSH   20      // xh position stride in u32 words (20g mod 32 distinct -> conflict-free)

// main-kernel smem: only the half2 halo tile
#define OFF_XH   0               // 180 pos * 20 u32 * 4B = 14400
#define SMEM_BYTES 14400

typedef unsigned int u32;

// ---- device scratch (precomputed layouts) ----
__device__ u32   BGg[32 * 4608];          // B f16 fragments per o (36 blk * 128 u32)
__device__ float BPSg[32 * 288];          // permuted predictor bias per o
__device__ u32   AGg[2 * 32 * 2048];      // A f16 fragments per (b, tile)
__device__ u32   XHg[2 * 4356 * 16];      // padded x, pixel-major half2: [b][yy*66+xx][c/2]

__device__ __forceinline__ u32 pkh2(float a, float b) {
    __half2 h = __floats2half2_rn(a, b);
    return *(u32*)&h;
}
__device__ __forceinline__ float2 uph2(u32 h) {
    return __half22float2(*(__half2*)&h);
}
__device__ __forceinline__ void mmaf16(float* d, const uint4& a, u32 b0, u32 b1) {
    asm volatile(
        "mma.sync.aligned.m16n8k16.row.col.f32.f16.f16.f32 "
        "{%0,%1,%2,%3}, {%4,%5,%6,%7}, {%8,%9}, {%0,%1,%2,%3};"
        : "+f"(d[0]), "+f"(d[1]), "+f"(d[2]), "+f"(d[3])
        : "r"(a.x), "r"(a.y), "r"(a.z), "r"(a.w), "r"(b0), "r"(b1));
}

// ================= Pre-pass: build all fragment layouts =================
__global__ void prepass(const float* __restrict__ x,
                        const float* __restrict__ Wp,
                        const float* __restrict__ bp)
{
    const u32 t0 = blockIdx.x * blockDim.x + threadIdx.x;
    const u32 stride = gridDim.x * blockDim.x;

    // B f16 fragments: 32 o * 36 blk(kk*4+oc) * 128 u32 (lane*4 + s)
    for (u32 idx = t0; idx < 32u * 4608u; idx += stride) {
        u32 o = idx / 4608u, i = idx - o * 4608u;
        u32 blk = i >> 7, w = i & 127u;
        u32 lane = w >> 2, s = w & 3u;
        u32 g = lane >> 2, q = lane & 3u;
        u32 kk = blk >> 2, oc = blk & 3u;
        u32 ks = s >> 1, r = s & 1u;
        u32 c = 8u * oc + g, cp = 16u * ks + 2u * q + 8u * r;
        const float* row = Wp + ((size_t)o * 288u + c * 9u + kk) * 32u + cp;
        BGg[idx] = pkh2(row[0], row[1]);
    }
    // permuted bias: 32 o * 288
    for (u32 idx = t0; idx < 32u * 288u; idx += stride) {
        u32 o = idx / 288u, j = idx - o * 288u;
        u32 c = j / 9u, kk = j - 9u * c;
        BPSg[o * 288 + kk * 32 + c] = bp[o * 288 + j];
    }
    // A f16 fragments: 2 b * 32 tiles * 16 blk(mtt*2+ks) * 128 u32
    for (u32 idx = t0; idx < 2u * 32u * 2048u; idx += stride) {
        u32 b = idx >> 16;
        u32 i = idx & 65535u;
        u32 tile = i >> 11, j = i & 2047u;
        u32 blk = j >> 7, w = j & 127u;
        u32 lane = w >> 2, s = w & 3u;
        u32 g = lane >> 2, q = lane & 3u;
        u32 mtt = blk >> 1, ks = blk & 1u;
        u32 tiley = tile >> 2, tilex = tile & 3u;
        u32 y = tiley * 8u + mtt;
        u32 xx = tilex * 16u + g + 8u * (s & 1u);
        u32 cp = 16u * ks + 2u * q + 8u * (s >> 1);
        float v0 = x[((size_t)(b * 32 + cp) * HDIM + y) * WDIM + xx];
        float v1 = x[((size_t)(b * 32 + cp + 1) * HDIM + y) * WDIM + xx];
        AGg[idx] = pkh2(v0, v1);
    }
    // padded pixel-major half2 x: 2 b * 66*66 pos * 16 words (c = 2w, 2w+1)
    for (u32 idx = t0; idx < 2u * 4356u * 16u; idx += stride) {
        u32 b = idx / 69696u;
        u32 rest = idx - b * 69696u;
        u32 pos = rest >> 4, w = rest & 15u;
        u32 yy = pos / 66u, xxp = pos - 66u * yy;
        float v0 = 0.0f, v1 = 0.0f;
        if (yy >= 1 && yy <= 64 && xxp >= 1 && xxp <= 64) {
            const float* px = x + ((size_t)(b * 32 + 2 * w) * HDIM + (yy - 1)) * WDIM + (xxp - 1);
            v0 = px[0];
            v1 = px[(size_t)HDIM * WDIM];
        }
        XHg[(size_t)b * 69696u + pos * 16u + w] = pkh2(v0, v1);
    }
}

// ================= Main kernel =================
__global__ __launch_bounds__(NTHR, 2)
void dyn_conv_f16(const float* __restrict__ x,
                  const float* __restrict__ Wp,
                  const float* __restrict__ bp,
                  float* __restrict__ out)
{
    extern __shared__ char sm[];
    u32* xh = (u32*)(sm + OFF_XH);

    const int bz = blockIdx.z;
    const int b  = bz >> 5;
    const int o  = bz & 31;
    const int x0 = blockIdx.x * TN;
    const int y0 = blockIdx.y * TM;
    const int tid  = threadIdx.x;
    const int lane = tid & 31;
    const int g = lane >> 2;
    const int q = lane & 3;
    const int mt = tid >> 5;       // warp = m-tile (pixel row y0+mt, 16 x-cols)
    const float bpo = bp[9216 + o];

    // ---- A fragments: 2 direct coalesced LDG.128 ----
    uint4 af[2];
    {
        const uint4* Aq = (const uint4*)AGg
            + (size_t)(b * 32 + blockIdx.y * 4 + blockIdx.x) * 512;
        #pragma unroll
        for (int ks = 0; ks < 2; ks++)
            af[ks] = Aq[(mt * 2 + ks) * 32 + lane];
    }
    // ---- half2 halo tile: 720 uint4 copies from padded image ----
    {
        const uint4* xg4 = (const uint4*)XHg + (size_t)b * 17424;
        #pragma unroll
        for (int j = 0; j < 3; j++) {
            u32 i = tid + j * NTHR;            // need 720
            if (i < 720) {
                u32 pos = i >> 2, c4 = i & 3;
                u32 r = pos / 18u, col = pos - 18u * r;
                uint4 v = xg4[((y0 + r) * 66 + x0 + col) * 4 + c4];
                *(uint4*)&xh[pos * XSH + 4 * c4] = v;
            }
        }
    }
    __syncthreads();

    // global fragment/bias bases (L1-resident: 64 CTAs share each o)
    const uint4*  Bg  = (const uint4*)BGg + (size_t)o * 1152 + lane;
    const float*  bpsg = BPSg + o * 288 + 2 * q;

    // ================= Fused single pass over kk =================
    const int txr0 = g, txr1 = g + 8;
    float s2[2][8], tp[2][8];
    #pragma unroll
    for (int r = 0; r < 2; r++)
        #pragma unroll
        for (int cl = 0; cl < 8; cl++) { s2[r][cl] = 0.0f; tp[r][cl] = 0.0f; }

    #pragma unroll
    for (int kk = 0; kk < 9; kk++) {
        const int dy = kk / 3, dx = kk - 3 * (kk / 3);
        const int pb0 = ((mt + dy) * 18 + txr0 + dx) * XSH + q;
        const int pb1 = ((mt + dy) * 18 + txr1 + dx) * XSH + q;

        // accs initialized with predictor bias (broadcast LDG.64, L1-hit)
        float accT[4][4];
        #pragma unroll
        for (int oc = 0; oc < 4; oc++) {
            float2 bv = *(const float2*)(bpsg + 32 * kk + 8 * oc);
            accT[oc][0] = bv.x; accT[oc][1] = bv.y;
            accT[oc][2] = bv.x; accT[oc][3] = bv.y;
        }
        // 4 independent c-octet tiles; B fragments straight from global (L1-hit)
        #pragma unroll
        for (int oc = 0; oc < 4; oc++) {
            uint4 bb = Bg[(kk * 4 + oc) * 32];     // LDG.128
            mmaf16(accT[oc], af[0], bb.x, bb.y);   // cp 0..15
            mmaf16(accT[oc], af[1], bb.z, bb.w);   // cp 16..31
        }
        // c-norm: per-thread partials + quad reduce (all 32 c live in-warp)
        float s1r0 = 0.0f, s1r1 = 0.0f;
        #pragma unroll
        for (int oc = 0; oc < 4; oc++) {
            s1r0 = fmaf(accT[oc][0], accT[oc][0], s1r0);
            s1r0 = fmaf(accT[oc][1], accT[oc][1], s1r0);
            s1r1 = fmaf(accT[oc][2], accT[oc][2], s1r1);
            s1r1 = fmaf(accT[oc][3], accT[oc][3], s1r1);
        }
        s1r0 += __shfl_xor_sync(0xffffffffu, s1r0, 1);
        s1r0 += __shfl_xor_sync(0xffffffffu, s1r0, 2);
        s1r1 += __shfl_xor_sync(0xffffffffu, s1r1, 1);
        s1r1 += __shfl_xor_sync(0xffffffffu, s1r1, 2);
        float inv1r0 = rsqrtf(fmaxf(s1r0, 1e-24f));   // == 1/max(sqrt,1e-12)
        float inv1r1 = rsqrtf(fmaxf(s1r1, 1e-24f));

        // scale by inv1; accumulate s2[c] and patch contraction (LDS.32 half2 pv)
        #pragma unroll
        for (int oc = 0; oc < 4; oc++) {
            float2 pv0 = uph2(xh[pb0 + 4 * oc]);   // conflict-free: banks 20g+4oc+q
            float2 pv1 = uph2(xh[pb1 + 4 * oc]);
            float d00 = accT[oc][0] * inv1r0;
            float d01 = accT[oc][1] * inv1r0;
            float d10 = accT[oc][2] * inv1r1;
            float d11 = accT[oc][3] * inv1r1;
            s2[0][2 * oc]     = fmaf(d00, d00, s2[0][2 * oc]);
            s2[0][2 * oc + 1] = fmaf(d01, d01, s2[0][2 * oc + 1]);
            s2[1][2 * oc]     = fmaf(d10, d10, s2[1][2 * oc]);
            s2[1][2 * oc + 1] = fmaf(d11, d11, s2[1][2 * oc + 1]);
            tp[0][2 * oc]     = fmaf(d00, pv0.x, tp[0][2 * oc]);
            tp[0][2 * oc + 1] = fmaf(d01, pv0.y, tp[0][2 * oc + 1]);
            tp[1][2 * oc]     = fmaf(d10, pv1.x, tp[1][2 * oc]);
            tp[1][2 * oc + 1] = fmaf(d11, pv1.y, tp[1][2 * oc + 1]);
        }
    }

    // ================= k-norm + dynamic bias + output =================
    const int cb0 = ((mt + 1) * 18 + txr0 + 1) * XSH + q;
    const int cb1 = ((mt + 1) * 18 + txr1 + 1) * XSH + q;
    const float* wpg = Wp + (size_t)(9216 + o) * 32 + 2 * q;
    float op0 = 0.0f, op1 = 0.0f;
    #pragma unroll
    for (int oc = 0; oc < 4; oc++) {
        float2 wv  = *(const float2*)(wpg + 8 * oc);   // L1-hit LDG.64
        float2 xc0 = uph2(xh[cb0 + 4 * oc]);
        float2 xc1 = uph2(xh[cb1 + 4 * oc]);
        op0 = fmaf(tp[0][2 * oc],     rsqrtf(fmaxf(s2[0][2 * oc],     1e-24f)), op0);
        op0 = fmaf(tp[0][2 * oc + 1], rsqrtf(fmaxf(s2[0][2 * oc + 1], 1e-24f)), op0);
        op1 = fmaf(tp[1][2 * oc],     rsqrtf(fmaxf(s2[1][2 * oc],     1e-24f)), op1);
        op1 = fmaf(tp[1][2 * oc + 1], rsqrtf(fmaxf(s2[1][2 * oc + 1], 1e-24f)), op1);
        op0 = fmaf(wv.x, xc0.x, op0);
        op0 = fmaf(wv.y, xc0.y, op0);
        op1 = fmaf(wv.x, xc1.x, op1);
        op1 = fmaf(wv.y, xc1.y, op1);
    }
    op0 += __shfl_xor_sync(0xffffffffu, op0, 1);
    op0 += __shfl_xor_sync(0xffffffffu, op0, 2);
    op1 += __shfl_xor_sync(0xffffffffu, op1, 1);
    op1 += __shfl_xor_sync(0xffffffffu, op1, 2);

    if (q == 0) {
        float* orow = out + (((size_t)b * COUT + o) * HDIM + (y0 + mt)) * WDIM + x0;
        orow[txr0] = op0 + bpo;
        orow[txr1] = op1 + bpo;
    }
}

extern "C" void kernel_launch(void* const* d_in, const int* in_sizes, int n_in,
                              void* d_out, int out_size)
{
    const float* x  = (const float*)d_in[0];   // (2, 32, 64, 64)
    const float* Wp = (const float*)d_in[1];   // (9248, 32)
    const float* bp = (const float*)d_in[2];   // (9248,)
    float* out = (float*)d_out;                // (2, 32, 64, 64)

    cudaFuncSetAttribute(dyn_conv_f16,
                         cudaFuncAttributeMaxDynamicSharedMemorySize, SMEM_BYTES);

    prepass<<<256, 256>>>(x, Wp, bp);

    dim3 grid(WDIM / TN, HDIM / TM, 2 * COUT);   // (4, 8, 64) -> 2048 CTAs
    dyn_conv_f16<<<grid, NTHR, SMEM_BYTES>>>(x, Wp, bp, out);
}

// round 15
// speedup vs baseline: 1.1816x; 1.1816x over previous
#include <cuda_runtime.h>
#include <cuda_fp16.h>
#include <cstdint>

#define CIN   32
#define COUT  32
#define HDIM  64
#define WDIM  64
#define NTHR  256
#define XSH   20      // xh position stride in u32 words (20g mod 32 distinct -> conflict-free)

// main-kernel smem byte offsets
#define OFF_B    0               // 36 blk * 512B        = 18432  (B f16 fragments)
#define OFF_XH   18432           // 324 pos * 20 u32 * 4 = 25920  (half2 halo, 18x18)
#define OFF_BPS  44352           // 288 * 4              = 1152
#define OFF_WPB  45504           // 32 * 4               = 128
#define SMEM_BYTES 45632

typedef unsigned int u32;

// ---- device scratch (precomputed layouts) ----
__device__ u32   BGg[32 * 4608];          // B f16 fragments per o (36 blk * 128 u32)
__device__ float BPSg[32 * 288];          // permuted predictor bias per o
__device__ u32   AGg[2 * 32 * 2048];      // A f16 fragments per (b, 8x16 tile)
__device__ u32   XHg[2 * 4356 * 16];      // padded x, pixel-major half2: [b][yy*66+xx][c/2]

__device__ __forceinline__ u32 pkh2(float a, float b) {
    __half2 h = __floats2half2_rn(a, b);
    return *(u32*)&h;
}
__device__ __forceinline__ float2 uph2(u32 h) {
    return __half22float2(*(__half2*)&h);
}
__device__ __forceinline__ void mmaf16(float* d, const uint4& a, u32 b0, u32 b1) {
    asm volatile(
        "mma.sync.aligned.m16n8k16.row.col.f32.f16.f16.f32 "
        "{%0,%1,%2,%3}, {%4,%5,%6,%7}, {%8,%9}, {%0,%1,%2,%3};"
        : "+f"(d[0]), "+f"(d[1]), "+f"(d[2]), "+f"(d[3])
        : "r"(a.x), "r"(a.y), "r"(a.z), "r"(a.w), "r"(b0), "r"(b1));
}

// ================= Pre-pass: build all fragment layouts =================
__global__ void prepass(const float* __restrict__ x,
                        const float* __restrict__ Wp,
                        const float* __restrict__ bp)
{
    const u32 t0 = blockIdx.x * blockDim.x + threadIdx.x;
    const u32 stride = gridDim.x * blockDim.x;

    // B f16 fragments: 32 o * 36 blk(kk*4+oc) * 128 u32 (lane*4 + s)
    for (u32 idx = t0; idx < 32u * 4608u; idx += stride) {
        u32 o = idx / 4608u, i = idx - o * 4608u;
        u32 blk = i >> 7, w = i & 127u;
        u32 lane = w >> 2, s = w & 3u;
        u32 g = lane >> 2, q = lane & 3u;
        u32 kk = blk >> 2, oc = blk & 3u;
        u32 ks = s >> 1, r = s & 1u;
        u32 c = 8u * oc + g, cp = 16u * ks + 2u * q + 8u * r;
        const float* row = Wp + ((size_t)o * 288u + c * 9u + kk) * 32u + cp;
        BGg[idx] = pkh2(row[0], row[1]);
    }
    // permuted bias: 32 o * 288
    for (u32 idx = t0; idx < 32u * 288u; idx += stride) {
        u32 o = idx / 288u, j = idx - o * 288u;
        u32 c = j / 9u, kk = j - 9u * c;
        BPSg[o * 288 + kk * 32 + c] = bp[o * 288 + j];
    }
    // A f16 fragments: 2 b * 32 tiles(8x16) * 16 blk(mtt*2+ks) * 128 u32
    for (u32 idx = t0; idx < 2u * 32u * 2048u; idx += stride) {
        u32 b = idx >> 16;
        u32 i = idx & 65535u;
        u32 tile = i >> 11, j = i & 2047u;
        u32 blk = j >> 7, w = j & 127u;
        u32 lane = w >> 2, s = w & 3u;
        u32 g = lane >> 2, q = lane & 3u;
        u32 mtt = blk >> 1, ks = blk & 1u;
        u32 tiley = tile >> 2, tilex = tile & 3u;
        u32 y = tiley * 8u + mtt;
        u32 xx = tilex * 16u + g + 8u * (s & 1u);
        u32 cp = 16u * ks + 2u * q + 8u * (s >> 1);
        float v0 = x[((size_t)(b * 32 + cp) * HDIM + y) * WDIM + xx];
        float v1 = x[((size_t)(b * 32 + cp + 1) * HDIM + y) * WDIM + xx];
        AGg[idx] = pkh2(v0, v1);
    }
    // padded pixel-major half2 x: 2 b * 66*66 pos * 16 words (c = 2w, 2w+1)
    for (u32 idx = t0; idx < 2u * 4356u * 16u; idx += stride) {
        u32 b = idx / 69696u;
        u32 rest = idx - b * 69696u;
        u32 pos = rest >> 4, w = rest & 15u;
        u32 yy = pos / 66u, xxp = pos - 66u * yy;
        float v0 = 0.0f, v1 = 0.0f;
        if (yy >= 1 && yy <= 64 && xxp >= 1 && xxp <= 64) {
            const float* px = x + ((size_t)(b * 32 + 2 * w) * HDIM + (yy - 1)) * WDIM + (xxp - 1);
            v0 = px[0];
            v1 = px[(size_t)HDIM * WDIM];
        }
        XHg[(size_t)b * 69696u + pos * 16u + w] = pkh2(v0, v1);
    }
}

// ================= Main kernel: one CTA = two stacked 8x16 tiles =================
__global__ __launch_bounds__(NTHR, 2)
void dyn_conv_f16(const float* __restrict__ x,
                  const float* __restrict__ Wp,
                  const float* __restrict__ bp,
                  float* __restrict__ out)
{
    extern __shared__ char sm[];
    u32*   xh  = (u32*)(sm + OFF_XH);
    float* bps = (float*)(sm + OFF_BPS);
    float* wpb = (float*)(sm + OFF_WPB);

    const int bz = blockIdx.z;
    const int b  = bz >> 5;
    const int o  = bz & 31;
    const int x0 = blockIdx.x * 16;
    const int y0 = blockIdx.y * 16;           // 16-row patch
    const int tid  = threadIdx.x;
    const int lane = tid & 31;
    const int g = lane >> 2;
    const int q = lane & 3;
    const int mt = tid >> 5;                  // warp = row within each half
    const float bpo = bp[9216 + o];

    // ---- A fragments for both halves (4 coalesced LDG.128) ----
    uint4 af[2][2];
    #pragma unroll
    for (int h = 0; h < 2; h++) {
        const uint4* Aq = (const uint4*)AGg
            + (size_t)(b * 32 + (blockIdx.y * 2 + h) * 4 + blockIdx.x) * 512;
        #pragma unroll
        for (int ks = 0; ks < 2; ks++)
            af[h][ks] = Aq[(mt * 2 + ks) * 32 + lane];
    }
    // ---- B fragments: pure copy global->smem (1152 uint4) ----
    {
        uint4* Bs4 = (uint4*)(sm + OFF_B);
        const uint4* Bg4 = (const uint4*)BGg + (size_t)o * 1152;
        #pragma unroll
        for (int j = 0; j < 5; j++) {
            int i = tid + j * NTHR;
            if (i < 1152) Bs4[i] = Bg4[i];
        }
    }
    // ---- half2 halo tile (18x18 pos): 1296 uint4 copies ----
    {
        const uint4* xg4 = (const uint4*)XHg + (size_t)b * 17424;
        #pragma unroll
        for (int j = 0; j < 6; j++) {
            u32 i = tid + j * NTHR;            // need 1296
            if (i < 1296) {
                u32 pos = i >> 2, c4 = i & 3;
                u32 r = pos / 18u, col = pos - 18u * r;
                uint4 v = xg4[((y0 + r) * 66 + x0 + col) * 4 + c4];
                *(uint4*)&xh[pos * XSH + 4 * c4] = v;
            }
        }
    }
    // ---- bias + wpb copies ----
    for (int i = tid; i < 288; i += NTHR) bps[i] = BPSg[o * 288 + i];
    if (tid < 32) wpb[tid] = Wp[(size_t)(9216 + o) * 32 + tid];
    __syncthreads();

    const uint4* Bq = (const uint4*)(sm + OFF_B);
    const int txr0 = g, txr1 = g + 8;

    #pragma unroll 1
    for (int h = 0; h < 2; h++) {
        const int rb = 8 * h;                 // row base within the 16-row patch

        float s2[2][8], tp[2][8];
        #pragma unroll
        for (int r = 0; r < 2; r++)
            #pragma unroll
            for (int cl = 0; cl < 8; cl++) { s2[r][cl] = 0.0f; tp[r][cl] = 0.0f; }

        #pragma unroll
        for (int kk = 0; kk < 9; kk++) {
            const int dy = kk / 3, dx = kk - 3 * (kk / 3);
            const int pb0 = ((rb + mt + dy) * 18 + txr0 + dx) * XSH + q;
            const int pb1 = ((rb + mt + dy) * 18 + txr1 + dx) * XSH + q;

            // accs initialized with predictor bias (broadcast LDS.64)
            float accT[4][4];
            #pragma unroll
            for (int oc = 0; oc < 4; oc++) {
                float2 bv = *(const float2*)&bps[32 * kk + 8 * oc + 2 * q];
                accT[oc][0] = bv.x; accT[oc][1] = bv.y;
                accT[oc][2] = bv.x; accT[oc][3] = bv.y;
            }
            // 4 independent c-octet tiles; 1 LDS.128 per (kk,oc)
            #pragma unroll
            for (int oc = 0; oc < 4; oc++) {
                uint4 bb = Bq[(kk * 4 + oc) * 32 + lane];
                mmaf16(accT[oc], af[h][0], bb.x, bb.y);   // cp 0..15
                mmaf16(accT[oc], af[h][1], bb.z, bb.w);   // cp 16..31
            }
            // c-norm: per-thread partials + quad reduce (all 32 c in-warp)
            float s1r0 = 0.0f, s1r1 = 0.0f;
            #pragma unroll
            for (int oc = 0; oc < 4; oc++) {
                s1r0 = fmaf(accT[oc][0], accT[oc][0], s1r0);
                s1r0 = fmaf(accT[oc][1], accT[oc][1], s1r0);
                s1r1 = fmaf(accT[oc][2], accT[oc][2], s1r1);
                s1r1 = fmaf(accT[oc][3], accT[oc][3], s1r1);
            }
            s1r0 += __shfl_xor_sync(0xffffffffu, s1r0, 1);
            s1r0 += __shfl_xor_sync(0xffffffffu, s1r0, 2);
            s1r1 += __shfl_xor_sync(0xffffffffu, s1r1, 1);
            s1r1 += __shfl_xor_sync(0xffffffffu, s1r1, 2);
            float inv1r0 = rsqrtf(fmaxf(s1r0, 1e-24f));   // == 1/max(sqrt,1e-12)
            float inv1r1 = rsqrtf(fmaxf(s1r1, 1e-24f));

            // scale by inv1; accumulate s2[c] and patch contraction
            #pragma unroll
            for (int oc = 0; oc < 4; oc++) {
                float2 pv0 = uph2(xh[pb0 + 4 * oc]);   // conflict-free banks
                float2 pv1 = uph2(xh[pb1 + 4 * oc]);
                float d00 = accT[oc][0] * inv1r0;
                float d01 = accT[oc][1] * inv1r0;
                float d10 = accT[oc][2] * inv1r1;
                float d11 = accT[oc][3] * inv1r1;
                s2[0][2 * oc]     = fmaf(d00, d00, s2[0][2 * oc]);
                s2[0][2 * oc + 1] = fmaf(d01, d01, s2[0][2 * oc + 1]);
                s2[1][2 * oc]     = fmaf(d10, d10, s2[1][2 * oc]);
                s2[1][2 * oc + 1] = fmaf(d11, d11, s2[1][2 * oc + 1]);
                tp[0][2 * oc]     = fmaf(d00, pv0.x, tp[0][2 * oc]);
                tp[0][2 * oc + 1] = fmaf(d01, pv0.y, tp[0][2 * oc + 1]);
                tp[1][2 * oc]     = fmaf(d10, pv1.x, tp[1][2 * oc]);
                tp[1][2 * oc + 1] = fmaf(d11, pv1.y, tp[1][2 * oc + 1]);
            }
        }

        // ---- k-norm + dynamic bias + output for this half ----
        const int cb0 = ((rb + mt + 1) * 18 + txr0 + 1) * XSH + q;
        const int cb1 = ((rb + mt + 1) * 18 + txr1 + 1) * XSH + q;
        float op0 = 0.0f, op1 = 0.0f;
        #pragma unroll
        for (int oc = 0; oc < 4; oc++) {
            float2 wv  = *(const float2*)&wpb[8 * oc + 2 * q];
            float2 xc0 = uph2(xh[cb0 + 4 * oc]);
            float2 xc1 = uph2(xh[cb1 + 4 * oc]);
            op0 = fmaf(tp[0][2 * oc],     rsqrtf(fmaxf(s2[0][2 * oc],     1e-24f)), op0);
            op0 = fmaf(tp[0][2 * oc + 1], rsqrtf(fmaxf(s2[0][2 * oc + 1], 1e-24f)), op0);
            op1 = fmaf(tp[1][2 * oc],     rsqrtf(fmaxf(s2[1][2 * oc],     1e-24f)), op1);
            op1 = fmaf(tp[1][2 * oc + 1], rsqrtf(fmaxf(s2[1][2 * oc + 1], 1e-24f)), op1);
            op0 = fmaf(wv.x, xc0.x, op0);
            op0 = fmaf(wv.y, xc0.y, op0);
            op1 = fmaf(wv.x, xc1.x, op1);
            op1 = fmaf(wv.y, xc1.y, op1);
        }
        op0 += __shfl_xor_sync(0xffffffffu, op0, 1);
        op0 += __shfl_xor_sync(0xffffffffu, op0, 2);
        op1 += __shfl_xor_sync(0xffffffffu, op1, 1);
        op1 += __shfl_xor_sync(0xffffffffu, op1, 2);

        if (q == 0) {
            float* orow = out + (((size_t)b * COUT + o) * HDIM + (y0 + rb + mt)) * WDIM + x0;
            orow[txr0] = op0 + bpo;
            orow[txr1] = op1 + bpo;
        }
    }
}

extern "C" void kernel_launch(void* const* d_in, const int* in_sizes, int n_in,
                              void* d_out, int out_size)
{
    const float* x  = (const float*)d_in[0];   // (2, 32, 64, 64)
    const float* Wp = (const float*)d_in[1];   // (9248, 32)
    const float* bp = (const float*)d_in[2];   // (9248,)
    float* out = (float*)d_out;                // (2, 32, 64, 64)

    cudaFuncSetAttribute(dyn_conv_f16,
                         cudaFuncAttributeMaxDynamicSharedMemorySize, SMEM_BYTES);

    prepass<<<256, 256>>>(x, Wp, bp);

    dim3 grid(4, 4, 64);                       // 16x16 patches -> 1024 CTAs
    dyn_conv_f16<<<grid, NTHR, SMEM_BYTES>>>(x, Wp, bp, out);
}